// round 12
// baseline (speedup 1.0000x reference)
#include <cuda_runtime.h>
#include <math.h>

#define H    512
#define NH   8
#define DH   64
#define TCTX 10
#define FFD  2048
#define NPREDC 26
#define MAXB 16
#define MAXF 5
#define MAXN 20
#define NB   296
#define NT   256
#define PB   128   // pairs per final unit
#define KZ   4     // final k-split

// ------------------------- device scratch -------------------------
__device__ float g_x  [MAXB * MAXF * H];
__device__ float g_ctx[MAXB * MAXF * H];
__device__ float g_qkv[2][MAXB * MAXF * 3 * H];
__device__ float g_qb [2][MAXB * MAXF * H];
__device__ float g_kv [2][MAXB * TCTX * 2 * H];
__device__ float g_ao [MAXB * MAXF * H];
__device__ float g_so [2][MAXB * MAXF * H];
__device__ float g_co [2][MAXB * MAXF * H];
__device__ float g_hh [2][MAXB * MAXF * FFD];
__device__ float g_ff [2][MAXB * MAXF * H];
__device__ float g_Sa [MAXB * MAXN * H];
__device__ float g_Sb [MAXB * MAXN * H];
__device__ float g_Sc [MAXB * MAXF * H];
__device__ float g_Wc [27 * H];
__device__ float g_bc [27];

__device__ unsigned g_count = 0;
__device__ unsigned g_gen   = 0;

struct Params {
    const float *tc, *objf, *fq;
    const float *sa_in_w, *sa_in_b, *sa_out_w, *sa_out_b;
    const float *ca_in_w, *ca_in_b, *ca_out_w, *ca_out_b;
    const float *ff1_w, *ff1_b, *ff2_w, *ff2_b;
    const float *n1_w, *n1_b, *n2_w, *n2_b, *n3_w, *n3_b, *norm_w, *norm_b;
    const float *pe1_w, *pe1_b, *pe2_w, *pe2_b, *pred_w, *pred_b, *ex_w, *ex_b;
    float *outp;
    int outn;
    int B, Nobj, Fh;
};

__device__ __forceinline__ float gelu_f(float x) {
    return 0.5f * x * (1.0f + erff(x * 0.70710678118654752440f));
}

__device__ __forceinline__ void fma2(float2& d, float2 a, float2 b) {
    asm("fma.rn.f32x2 %0, %1, %2, %0;"
        : "+l"(reinterpret_cast<unsigned long long&>(d))
        : "l"(reinterpret_cast<unsigned long long&>(a)),
          "l"(reinterpret_cast<unsigned long long&>(b)));
}

// simple grid barrier (R8-verified)
__device__ __forceinline__ void gsync() {
    __syncthreads();
    if (threadIdx.x == 0) {
        __threadfence();
        unsigned gen = *((volatile unsigned*)&g_gen);
        if (atomicAdd(&g_count, 1) == gridDim.x - 1) {
            g_count = 0;
            __threadfence();
            atomicAdd(&g_gen, 1);
        } else {
            while (*((volatile unsigned*)&g_gen) == gen) { __nanosleep(32); }
            __threadfence();
        }
    }
    __syncthreads();
}

// ---- 80x64 GEMM tile over a 64-wide K slice, atomic out ----
#define PA 84
#define PW 66
__device__ void gemm_unit(const float* __restrict__ A, int lda, const float* __restrict__ ab,
                          const float* __restrict__ W, int ldw,
                          float* __restrict__ C, int ldc,
                          int row0, int n0, int kb,
                          float2* sA2, float2* sW2, int tid)
{
    const int rg = tid >> 4;
    const int cg = tid & 15;
    float2 acc[5][4];
    #pragma unroll
    for (int j = 0; j < 5; j++)
        #pragma unroll
        for (int q = 0; q < 4; q++) acc[j][q] = make_float2(0.f, 0.f);

    const int ar1 = tid >> 3,          ak1 = tid & 7;
    const int ar2 = (tid + 256) >> 3,  ak2 = tid & 7;
    const int ar3 = (tid + 512) >> 3,  ak3 = tid & 7;
    const int wn1 = tid >> 3,          wk1 = tid & 7;
    const int wn2 = (tid + 256) >> 3,  wk2 = tid & 7;
    float4 a1, a2, a3, w1, w2;

    auto loadRegs = [&](int k0) {
        a1 = *(const float4*)(A + (size_t)(row0 + ar1) * lda + k0 + 4 * ak1);
        a2 = *(const float4*)(A + (size_t)(row0 + ar2) * lda + k0 + 4 * ak2);
        if (tid < 128)
            a3 = *(const float4*)(A + (size_t)(row0 + ar3) * lda + k0 + 4 * ak3);
        if (ab) {
            const float* b1 = ab + k0 + 4 * ak1;
            a1.x = gelu_f(a1.x + b1[0]); a1.y = gelu_f(a1.y + b1[1]);
            a1.z = gelu_f(a1.z + b1[2]); a1.w = gelu_f(a1.w + b1[3]);
            a2.x = gelu_f(a2.x + b1[0]); a2.y = gelu_f(a2.y + b1[1]);
            a2.z = gelu_f(a2.z + b1[2]); a2.w = gelu_f(a2.w + b1[3]);
            if (tid < 128) {
                a3.x = gelu_f(a3.x + b1[0]); a3.y = gelu_f(a3.y + b1[1]);
                a3.z = gelu_f(a3.z + b1[2]); a3.w = gelu_f(a3.w + b1[3]);
            }
        }
        w1 = *(const float4*)(W + (size_t)(n0 + wn1) * ldw + k0 + 4 * wk1);
        w2 = *(const float4*)(W + (size_t)(n0 + wn2) * ldw + k0 + 4 * wk2);
    };
    auto storeRegs = [&]() {
        sA2[(2 * ak1)     * PA + ar1] = make_float2(a1.x, a1.y);
        sA2[(2 * ak1 + 1) * PA + ar1] = make_float2(a1.z, a1.w);
        sA2[(2 * ak2)     * PA + ar2] = make_float2(a2.x, a2.y);
        sA2[(2 * ak2 + 1) * PA + ar2] = make_float2(a2.z, a2.w);
        if (tid < 128) {
            sA2[(2 * ak3)     * PA + ar3] = make_float2(a3.x, a3.y);
            sA2[(2 * ak3 + 1) * PA + ar3] = make_float2(a3.z, a3.w);
        }
        sW2[(2 * wk1)     * PW + wn1] = make_float2(w1.x, w1.y);
        sW2[(2 * wk1 + 1) * PW + wn1] = make_float2(w1.z, w1.w);
        sW2[(2 * wk2)     * PW + wn2] = make_float2(w2.x, w2.y);
        sW2[(2 * wk2 + 1) * PW + wn2] = make_float2(w2.z, w2.w);
    };

    loadRegs(kb);
    #pragma unroll
    for (int c = 0; c < 2; c++) {
        storeRegs();
        __syncthreads();
        if (c < 1) loadRegs(kb + 32);
        #pragma unroll
        for (int kp = 0; kp < 16; kp++) {
            const float4* wp = (const float4*)(sW2 + kp * PW + 4 * cg);
            float4 wA = wp[0], wB = wp[1];
            float2 w0 = make_float2(wA.x, wA.y), wb1 = make_float2(wA.z, wA.w);
            float2 w2v = make_float2(wB.x, wB.y), w3 = make_float2(wB.z, wB.w);
            const float2* ap = sA2 + kp * PA + 5 * rg;
            #pragma unroll
            for (int j = 0; j < 5; j++) {
                float2 aj = ap[j];
                fma2(acc[j][0], aj, w0);
                fma2(acc[j][1], aj, wb1);
                fma2(acc[j][2], aj, w2v);
                fma2(acc[j][3], aj, w3);
            }
        }
        __syncthreads();
    }

    #pragma unroll
    for (int j = 0; j < 5; j++) {
        float* Cp = C + (size_t)(row0 + 5 * rg + j) * ldc + n0 + 4 * cg;
        atomicAdd(Cp + 0, acc[j][0].x + acc[j][0].y);
        atomicAdd(Cp + 1, acc[j][1].x + acc[j][1].y);
        atomicAdd(Cp + 2, acc[j][2].x + acc[j][2].y);
        atomicAdd(Cp + 3, acc[j][3].x + acc[j][3].y);
    }
}

// ---- final pair-GEMM unit (R10-verified body), one (px, bf, z) tile ----
struct FinalSmem {
    float sG[32 * (PB + 4)];
    float sWc[32 * 34];
    float sSc[H / KZ];
    int2  sIJ[PB];
};
__device__ void final_unit(const float* __restrict__ pe1b,
                           float* __restrict__ out_pred, float* __restrict__ out_ex,
                           int Nobj, int P, int Fh,
                           int px, int bf, int z, FinalSmem* fs, int tid)
{
    const int b = bf / Fh;
    const int p0 = px * PB;
    const int kz0 = z * (H / KZ);

    for (int i = tid; i < H / KZ; i += 256)
        fs->sSc[i] = g_Sc[(size_t)bf * H + kz0 + i] + pe1b[kz0 + i];
    if (tid < PB) {
        int nm1 = Nobj - 1;
        int pp = p0 + tid; if (pp >= P) pp = P - 1;
        int i = pp / nm1, r = pp % nm1; int j = (r < i) ? r : r + 1;
        fs->sIJ[tid] = make_int2(i, j);
    }
    __syncthreads();

    const int spair = tid >> 1;
    const int skh   = tid & 1;
    const float* saRow = g_Sa + (size_t)(b * Nobj + fs->sIJ[spair].x) * H + kz0;
    const float* sbRow = g_Sb + (size_t)(b * Nobj + fs->sIJ[spair].y) * H + kz0;

    const int pg = tid & 31;
    const int rg = tid >> 5;
    float2 acc[4][4];
    #pragma unroll
    for (int q = 0; q < 4; q++)
        #pragma unroll
        for (int s = 0; s < 4; s++) acc[q][s] = make_float2(0.f, 0.f);

    for (int kc = 0; kc < H / KZ; kc += 32) {
        #pragma unroll
        for (int j = 0; j < 4; j++) {
            int i = tid + j * 256;
            int r = i >> 5, k = i & 31;
            fs->sWc[r * 34 + k] = (r < 27) ? g_Wc[r * H + kz0 + kc + k] : 0.f;
        }
        #pragma unroll
        for (int j = 0; j < 4; j++) {
            int k = skh * 16 + j * 4;
            float4 a  = *(const float4*)(saRow + kc + k);
            float4 bv = *(const float4*)(sbRow + kc + k);
            float4 c4 = *(const float4*)(fs->sSc + kc + k);
            fs->sG[(k + 0) * (PB + 4) + spair] = gelu_f(a.x + bv.x + c4.x);
            fs->sG[(k + 1) * (PB + 4) + spair] = gelu_f(a.y + bv.y + c4.y);
            fs->sG[(k + 2) * (PB + 4) + spair] = gelu_f(a.z + bv.z + c4.z);
            fs->sG[(k + 3) * (PB + 4) + spair] = gelu_f(a.w + bv.w + c4.w);
        }
        __syncthreads();
        #pragma unroll
        for (int kk = 0; kk < 16; kk++) {
            float4 gA = *(const float4*)&fs->sG[(2 * kk)     * (PB + 4) + 4 * pg];
            float4 gB = *(const float4*)&fs->sG[(2 * kk + 1) * (PB + 4) + 4 * pg];
            float2 gp[4] = { make_float2(gA.x, gB.x), make_float2(gA.y, gB.y),
                             make_float2(gA.z, gB.z), make_float2(gA.w, gB.w) };
            #pragma unroll
            for (int s = 0; s < 4; s++) {
                float2 w = *(const float2*)&fs->sWc[(4 * rg + s) * 34 + 2 * kk];
                fma2(acc[0][s], gp[0], w);
                fma2(acc[1][s], gp[1], w);
                fma2(acc[2][s], gp[2], w);
                fma2(acc[3][s], gp[3], w);
            }
        }
        __syncthreads();
    }

    const float biasOn = (z == 0) ? 1.f : 0.f;
    #pragma unroll
    for (int q = 0; q < 4; q++) {
        int pair = p0 + 4 * pg + q;
        if (pair >= P) continue;
        size_t base = (size_t)bf * P + pair;
        #pragma unroll
        for (int s = 0; s < 4; s++) {
            int r = 4 * rg + s;
            if (r >= 27) continue;
            float v = acc[q][s].x + acc[q][s].y + biasOn * g_bc[r];
            if (r < NPREDC) atomicAdd(&out_pred[base * 26 + r], v);
            else            atomicAdd(&out_ex[base], v);
        }
    }
}

// ------------------------- persistent decoder (single kernel) -------------------------
__global__ __launch_bounds__(NT, 2) void decoder_kernel(Params p)
{
    __shared__ float2 sA[16 * PA];
    __shared__ float2 sW[16 * PW];
    __shared__ FinalSmem fsm;
    const int tid = threadIdx.x, bid = blockIdx.x;
    const int lane = tid & 31;
    const int gw = bid * (NT / 32) + (tid >> 5);
    const int GW = gridDim.x * (NT / 32);
    const int GB = gridDim.x;
    const int M = p.B * p.Fh;
    const int Fh = p.Fh;

    auto zero4 = [&](float* pz, int n) {
        float4* z = (float4*)pz;
        int t4 = n >> 2;
        for (int i = bid * NT + tid; i < t4; i += GB * NT)
            z[i] = make_float4(0.f, 0.f, 0.f, 0.f);
    };
    auto gemm_stage = [&](const float* A, int lda, const float* ab,
                          const float* W, int ldw, float* C, int ldc,
                          int mt, int nt, int kz) {
        int total = mt * nt * kz;
        for (int u = bid; u < total; u += GB) {
            int m = u % mt; int n = (u / mt) % nt; int z = u / (mt * nt);
            gemm_unit(A, lda, ab, W, ldw, C, ldc, m * 80, n * 64, z * 64, sA, sW, tid);
        }
    };
    auto attn_stage = [&](const float* Q, int ldq, const float* qb,
                          const float* K, const float* V, int ldkv,
                          const float* kb, const float* vb, int Tq, int Tk) {
        for (int u = gw; u < p.B * NH * Tq; u += GW) {
            int qi = u % Tq; int h = (u / Tq) % NH; int b = u / (Tq * NH);
            const float* qrow = Q + (size_t)(b * Tq + qi) * ldq + h * DH;
            float q0 = qrow[lane]      + qb[h * DH + lane];
            float q1 = qrow[lane + 32] + qb[h * DH + lane + 32];
            float kb0 = kb[h * DH + lane], kb1 = kb[h * DH + lane + 32];
            float vb0 = vb[h * DH + lane], vb1 = vb[h * DH + lane + 32];
            float s[TCTX];
            #pragma unroll
            for (int k = 0; k < TCTX; k++) {
                if (k < Tk) {
                    const float* krow = K + (size_t)(b * Tk + k) * ldkv + h * DH;
                    float pr = q0 * (krow[lane] + kb0) + q1 * (krow[lane + 32] + kb1);
                    #pragma unroll
                    for (int o = 16; o; o >>= 1) pr += __shfl_xor_sync(0xffffffffu, pr, o);
                    s[k] = pr * 0.125f;
                }
            }
            float mx = -1e30f;
            #pragma unroll
            for (int k = 0; k < TCTX; k++) if (k < Tk) mx = fmaxf(mx, s[k]);
            float sum = 0.f;
            #pragma unroll
            for (int k = 0; k < TCTX; k++) if (k < Tk) { s[k] = expf(s[k] - mx); sum += s[k]; }
            float inv = 1.f / sum;
            float o0 = 0.f, o1 = 0.f;
            #pragma unroll
            for (int k = 0; k < TCTX; k++) {
                if (k < Tk) {
                    const float* vrow = V + (size_t)(b * Tk + k) * ldkv + h * DH;
                    float a = s[k] * inv;
                    o0 += a * (vrow[lane] + vb0);
                    o1 += a * (vrow[lane + 32] + vb1);
                }
            }
            float* orow = g_ao + (size_t)(b * Tq + qi) * H + h * DH;
            orow[lane]      = o0;
            orow[lane + 32] = o1;
        }
    };
    auto ln_stage = [&](const float* src, const float* res, const float* cb,
                        float* dst, const float* w, const float* bnb) {
        for (int row = gw; row < M; row += GW) {
            const float* xr = src + (size_t)row * H;
            float4 v[4];
            float s = 0.f;
            #pragma unroll
            for (int i = 0; i < 4; i++) {
                int c = i * 128 + lane * 4;
                float4 t = *(const float4*)&xr[c];
                if (res) { float4 r = *(const float4*)&res[(size_t)row * H + c];
                           t.x += r.x; t.y += r.y; t.z += r.z; t.w += r.w; }
                if (cb)  { float4 b4 = *(const float4*)&cb[c];
                           t.x += b4.x; t.y += b4.y; t.z += b4.z; t.w += b4.w; }
                v[i] = t; s += t.x + t.y + t.z + t.w;
            }
            #pragma unroll
            for (int o = 16; o; o >>= 1) s += __shfl_xor_sync(0xffffffffu, s, o);
            float mean = s * (1.0f / H);
            float q = 0.f;
            #pragma unroll
            for (int i = 0; i < 4; i++) {
                float dx = v[i].x - mean, dy = v[i].y - mean, dz = v[i].z - mean, dw = v[i].w - mean;
                q += dx * dx + dy * dy + dz * dz + dw * dw;
            }
            #pragma unroll
            for (int o = 16; o; o >>= 1) q += __shfl_xor_sync(0xffffffffu, q, o);
            float inv = 1.0f / sqrtf(q * (1.0f / H) + 1e-5f);
            #pragma unroll
            for (int i = 0; i < 4; i++) {
                int c = i * 128 + lane * 4;
                float4 w4 = *(const float4*)&w[c];
                float4 b4 = *(const float4*)&bnb[c];
                float4 o4;
                o4.x = (v[i].x - mean) * inv * w4.x + b4.x;
                o4.y = (v[i].y - mean) * inv * w4.y + b4.y;
                o4.z = (v[i].z - mean) * inv * w4.z + b4.z;
                o4.w = (v[i].w - mean) * inv * w4.w + b4.w;
                *(float4*)&dst[(size_t)row * H + c] = o4;
            }
        }
    };

    // ---- Z0 ----
    zero4(g_qkv[0], M * 3 * H);  zero4(g_qkv[1], M * 3 * H);
    zero4(g_qb[0],  M * H);      zero4(g_qb[1],  M * H);
    zero4(g_kv[0],  p.B * TCTX * 2 * H); zero4(g_kv[1], p.B * TCTX * 2 * H);
    zero4(g_so[0],  M * H);      zero4(g_so[1],  M * H);
    zero4(g_co[0],  M * H);      zero4(g_co[1],  M * H);
    zero4(g_hh[0],  M * FFD);    zero4(g_hh[1],  M * FFD);
    zero4(g_ff[0],  M * H);      zero4(g_ff[1],  M * H);
    zero4(g_Sa, p.B * p.Nobj * H); zero4(g_Sb, p.B * p.Nobj * H);
    zero4(g_Sc, M * H);
    zero4(p.outp, p.outn);
    for (int i = bid * NT + tid; i < M * H; i += GB * NT) {
        int row = i / H, c = i % H;
        g_x[i] = p.fq[(row % Fh) * H + c];
    }
    for (int u = gw; u < 27 * 16; u += GW) {
        int rr = u / 16, cgp = u % 16;
        const float* Pr = (rr < NPREDC) ? (p.pred_w + rr * H) : p.ex_w;
        int c = cgp * 32 + lane;
        float a0 = 0.f, a1 = 0.f, a2 = 0.f, a3 = 0.f;
        for (int n = 0; n < H; n += 4) {
            a0 += Pr[n]     * p.pe2_w[(size_t)n * H + c];
            a1 += Pr[n + 1] * p.pe2_w[(size_t)(n + 1) * H + c];
            a2 += Pr[n + 2] * p.pe2_w[(size_t)(n + 2) * H + c];
            a3 += Pr[n + 3] * p.pe2_w[(size_t)(n + 3) * H + c];
        }
        g_Wc[rr * H + c] = (a0 + a1) + (a2 + a3);
    }
    for (int u = gw; u < 27; u += GW) {
        const float* Pr = (u < NPREDC) ? (p.pred_w + u * H) : p.ex_w;
        float s = 0.f;
        for (int n = lane; n < H; n += 32) s += Pr[n] * p.pe2_b[n];
        #pragma unroll
        for (int o = 16; o; o >>= 1) s += __shfl_xor_sync(0xffffffffu, s, o);
        if (lane == 0) g_bc[u] = s + ((u < NPREDC) ? p.pred_b[u] : p.ex_b[0]);
    }
    gsync();

    const int mS = (p.B * p.Nobj) / 80;
    const int mKV = (p.B * TCTX) / 80;

    // ---- S1 ----
    gemm_stage(g_x, H, nullptr, p.sa_in_w, H, g_qkv[0], 3 * H, 1, 3 * H / 64, 8);
    gemm_stage(p.objf, H, nullptr, p.pe1_w,     3 * H, g_Sa, H, mS, 8, 8);
    gemm_stage(p.objf, H, nullptr, p.pe1_w + H, 3 * H, g_Sb, H, mS, 8, 8);
    gemm_stage(p.tc, H, nullptr, p.ca_in_w + (size_t)H * H, H, g_kv[0], 2 * H, mKV, 2 * H / 64, 8);
    gsync();

    for (int l = 0; l < 2; l++) {
        const float* siw = p.sa_in_w  + (size_t)l * 3 * H * H;
        const float* sib = p.sa_in_b  + (size_t)l * 3 * H;
        const float* sow = p.sa_out_w + (size_t)l * H * H;
        const float* sob = p.sa_out_b + (size_t)l * H;
        const float* ciw = p.ca_in_w  + (size_t)l * 3 * H * H;
        const float* cib = p.ca_in_b  + (size_t)l * 3 * H;
        const float* cow = p.ca_out_w + (size_t)l * H * H;
        const float* cob = p.ca_out_b + (size_t)l * H;
        const float* f1w = p.ff1_w    + (size_t)l * FFD * H;
        const float* f1b = p.ff1_b    + (size_t)l * FFD;
        const float* f2w = p.ff2_w    + (size_t)l * H * FFD;
        const float* f2b = p.ff2_b    + (size_t)l * H;

        if (l == 1) {
            gemm_stage(g_x, H, nullptr, siw, H, g_qkv[1], 3 * H, 1, 3 * H / 64, 8);
            gemm_stage(p.tc, H, nullptr, ciw + (size_t)H * H, H, g_kv[1], 2 * H, mKV, 2 * H / 64, 8);
            gsync();
        }
        attn_stage(g_qkv[l], 3 * H, sib, g_qkv[l] + H, g_qkv[l] + 2 * H, 3 * H,
                   sib + H, sib + 2 * H, Fh, Fh);
        gsync();
        gemm_stage(g_ao, H, nullptr, sow, H, g_so[l], H, 1, 8, 8);
        gsync();
        ln_stage(g_so[l], g_x, sob, g_x, p.n1_w + l * H, p.n1_b + l * H);
        gsync();
        gemm_stage(g_x, H, nullptr, ciw, H, g_qb[l], H, 1, 8, 8);
        gsync();
        attn_stage(g_qb[l], H, cib, g_kv[l], g_kv[l] + H, 2 * H,
                   cib + H, cib + 2 * H, Fh, TCTX);
        gsync();
        gemm_stage(g_ao, H, nullptr, cow, H, g_co[l], H, 1, 8, 8);
        gsync();
        ln_stage(g_co[l], g_x, cob, g_x, p.n2_w + l * H, p.n2_b + l * H);
        gsync();
        gemm_stage(g_x, H, nullptr, f1w, H, g_hh[l], FFD, 1, FFD / 64, 8);
        gsync();
        gemm_stage(g_hh[l], FFD, f1b, f2w, FFD, g_ff[l], H, 1, 8, FFD / 64);
        gsync();
        ln_stage(g_ff[l], g_x, f2b, g_x, p.n3_w + l * H, p.n3_b + l * H);
        gsync();
    }

    ln_stage(g_x, nullptr, nullptr, g_ctx, p.norm_w, p.norm_b);
    gsync();
    gemm_stage(g_ctx, H, nullptr, p.pe1_w + 2 * H, 3 * H, g_Sc, H, 1, 8, 8);
    gsync();

    // ---- final stage: pair GEMM into d_out ----
    {
        int P = p.Nobj * (p.Nobj - 1);
        int PBx = (P + PB - 1) / PB;
        float* out_pred = p.outp;
        float* out_ex   = p.outp + (size_t)p.B * p.Fh * P * NPREDC;
        int total = PBx * M * KZ;
        for (int u = bid; u < total; u += GB) {
            int px = u % PBx;
            int bf = (u / PBx) % M;
            int z  = u / (PBx * M);
            final_unit(p.pe1_b, out_pred, out_ex, p.Nobj, P, Fh, px, bf, z, &fsm, tid);
        }
    }
}

// ------------------------- host launcher -------------------------
extern "C" void kernel_launch(void* const* d_in, const int* in_sizes, int n_in,
                              void* d_out, int out_size)
{
    Params p;
    p.tc       = (const float*)d_in[0];
    p.objf     = (const float*)d_in[1];
    p.fq       = (const float*)d_in[2];
    p.sa_in_w  = (const float*)d_in[3];
    p.sa_in_b  = (const float*)d_in[4];
    p.sa_out_w = (const float*)d_in[5];
    p.sa_out_b = (const float*)d_in[6];
    p.ca_in_w  = (const float*)d_in[7];
    p.ca_in_b  = (const float*)d_in[8];
    p.ca_out_w = (const float*)d_in[9];
    p.ca_out_b = (const float*)d_in[10];
    p.ff1_w    = (const float*)d_in[11];
    p.ff1_b    = (const float*)d_in[12];
    p.ff2_w    = (const float*)d_in[13];
    p.ff2_b    = (const float*)d_in[14];
    p.n1_w     = (const float*)d_in[15];
    p.n1_b     = (const float*)d_in[16];
    p.n2_w     = (const float*)d_in[17];
    p.n2_b     = (const float*)d_in[18];
    p.n3_w     = (const float*)d_in[19];
    p.n3_b     = (const float*)d_in[20];
    p.norm_w   = (const float*)d_in[21];
    p.norm_b   = (const float*)d_in[22];
    p.pe1_w    = (const float*)d_in[23];
    p.pe1_b    = (const float*)d_in[24];
    p.pe2_w    = (const float*)d_in[25];
    p.pe2_b    = (const float*)d_in[26];
    p.pred_w   = (const float*)d_in[27];
    p.pred_b   = (const float*)d_in[28];
    p.ex_w     = (const float*)d_in[29];
    p.ex_b     = (const float*)d_in[30];

    p.B    = in_sizes[0] / (TCTX * H);
    p.Nobj = in_sizes[1] / (p.B * H);
    int P  = p.Nobj * (p.Nobj - 1);
    p.Fh   = out_size / (p.B * P * (NPREDC + 1));
    p.outp = (float*)d_out;
    p.outn = out_size;

    decoder_kernel<<<NB, NT>>>(p);
}

// round 13
// speedup vs baseline: 1.0925x; 1.0925x over previous
#include <cuda_runtime.h>
#include <math.h>

#define H    512
#define NH   8
#define DH   64
#define TCTX 10
#define FFD  2048
#define NPREDC 26
#define MAXB 16
#define MAXF 5
#define MAXN 20
#define NB   444
#define NT   256
#define PB   128   // pairs per final unit
#define KZ   4     // final k-split

// ------------------------- device scratch -------------------------
__device__ float g_x  [MAXB * MAXF * H];
__device__ float g_ctx[MAXB * MAXF * H];
__device__ float g_qkv[2][MAXB * MAXF * 3 * H];
__device__ float g_qb [2][MAXB * MAXF * H];
__device__ float g_kv [2][MAXB * TCTX * 2 * H];
__device__ float g_ao [MAXB * MAXF * H];
__device__ float g_so [2][MAXB * MAXF * H];
__device__ float g_co [2][MAXB * MAXF * H];
__device__ float g_hh [2][MAXB * MAXF * FFD];
__device__ float g_ff [2][MAXB * MAXF * H];
__device__ float g_Sa [MAXB * MAXN * H];
__device__ float g_Sb [MAXB * MAXN * H];
__device__ float g_Sc [MAXB * MAXF * H];
__device__ float g_Wc [27 * H];
__device__ float g_bc [27];

__device__ unsigned g_count = 0;
__device__ unsigned g_gen   = 0;

struct Params {
    const float *tc, *objf, *fq;
    const float *sa_in_w, *sa_in_b, *sa_out_w, *sa_out_b;
    const float *ca_in_w, *ca_in_b, *ca_out_w, *ca_out_b;
    const float *ff1_w, *ff1_b, *ff2_w, *ff2_b;
    const float *n1_w, *n1_b, *n2_w, *n2_b, *n3_w, *n3_b, *norm_w, *norm_b;
    const float *pe1_w, *pe1_b, *pe2_w, *pe2_b, *pred_w, *pred_b, *ex_w, *ex_b;
    float *outp;
    int outn;
    int B, Nobj, Fh;
};

__device__ __forceinline__ float gelu_f(float x) {
    return 0.5f * x * (1.0f + erff(x * 0.70710678118654752440f));
}

__device__ __forceinline__ void fma2(float2& d, float2 a, float2 b) {
    asm("fma.rn.f32x2 %0, %1, %2, %0;"
        : "+l"(reinterpret_cast<unsigned long long&>(d))
        : "l"(reinterpret_cast<unsigned long long&>(a)),
          "l"(reinterpret_cast<unsigned long long&>(b)));
}

// simple grid barrier (R8-verified)
__device__ __forceinline__ void gsync() {
    __syncthreads();
    if (threadIdx.x == 0) {
        __threadfence();
        unsigned gen = *((volatile unsigned*)&g_gen);
        if (atomicAdd(&g_count, 1) == gridDim.x - 1) {
            g_count = 0;
            __threadfence();
            atomicAdd(&g_gen, 1);
        } else {
            while (*((volatile unsigned*)&g_gen) == gen) { __nanosleep(32); }
            __threadfence();
        }
    }
    __syncthreads();
}

// ---- 80x32 GEMM tile over a 64-wide K slice, atomic out ----
// smem: sA2[16 kp][PA] float2 (80 rows), sW2[16 kp][PW2] float2 (32 n).
// thread: 5 rows x 2 cols (rg=tid>>4 -> rows 5rg..5rg+4; cg=tid&15 -> cols 2cg,2cg+1).
#define PA  84
#define PW2 34
__device__ void gemm_unit(const float* __restrict__ A, int lda, const float* __restrict__ ab,
                          const float* __restrict__ W, int ldw,
                          float* __restrict__ C, int ldc,
                          int row0, int n0, int kb,
                          float2* sA2, float2* sW2, int tid)
{
    const int rg = tid >> 4;
    const int cg = tid & 15;
    float2 acc[5][2];
    #pragma unroll
    for (int j = 0; j < 5; j++) { acc[j][0] = make_float2(0.f, 0.f); acc[j][1] = make_float2(0.f, 0.f); }

    // A: 640 float4/chunk (80 rows x 8 quads) -> 2.5 per thread
    const int ar1 = tid >> 3,          ak1 = tid & 7;
    const int ar2 = (tid + 256) >> 3,  ak2 = tid & 7;
    const int ar3 = (tid + 512) >> 3,  ak3 = tid & 7;
    // W: 256 float4/chunk (32 n x 8 quads) -> 1 per thread
    const int wn = tid >> 3,           wk = tid & 7;
    float4 a1, a2, a3, w1;

    auto loadRegs = [&](int k0) {
        a1 = *(const float4*)(A + (size_t)(row0 + ar1) * lda + k0 + 4 * ak1);
        a2 = *(const float4*)(A + (size_t)(row0 + ar2) * lda + k0 + 4 * ak2);
        if (tid < 128)
            a3 = *(const float4*)(A + (size_t)(row0 + ar3) * lda + k0 + 4 * ak3);
        if (ab) {
            const float* b1 = ab + k0 + 4 * ak1;
            a1.x = gelu_f(a1.x + b1[0]); a1.y = gelu_f(a1.y + b1[1]);
            a1.z = gelu_f(a1.z + b1[2]); a1.w = gelu_f(a1.w + b1[3]);
            a2.x = gelu_f(a2.x + b1[0]); a2.y = gelu_f(a2.y + b1[1]);
            a2.z = gelu_f(a2.z + b1[2]); a2.w = gelu_f(a2.w + b1[3]);
            if (tid < 128) {
                a3.x = gelu_f(a3.x + b1[0]); a3.y = gelu_f(a3.y + b1[1]);
                a3.z = gelu_f(a3.z + b1[2]); a3.w = gelu_f(a3.w + b1[3]);
            }
        }
        w1 = *(const float4*)(W + (size_t)(n0 + wn) * ldw + k0 + 4 * wk);
    };
    auto storeRegs = [&]() {
        sA2[(2 * ak1)     * PA + ar1] = make_float2(a1.x, a1.y);
        sA2[(2 * ak1 + 1) * PA + ar1] = make_float2(a1.z, a1.w);
        sA2[(2 * ak2)     * PA + ar2] = make_float2(a2.x, a2.y);
        sA2[(2 * ak2 + 1) * PA + ar2] = make_float2(a2.z, a2.w);
        if (tid < 128) {
            sA2[(2 * ak3)     * PA + ar3] = make_float2(a3.x, a3.y);
            sA2[(2 * ak3 + 1) * PA + ar3] = make_float2(a3.z, a3.w);
        }
        sW2[(2 * wk)     * PW2 + wn] = make_float2(w1.x, w1.y);
        sW2[(2 * wk + 1) * PW2 + wn] = make_float2(w1.z, w1.w);
    };

    loadRegs(kb);
    #pragma unroll
    for (int c = 0; c < 2; c++) {
        storeRegs();
        __syncthreads();
        if (c < 1) loadRegs(kb + 32);
        #pragma unroll
        for (int kp = 0; kp < 16; kp++) {
            float4 wv = *(const float4*)&sW2[kp * PW2 + 2 * cg];   // n=2cg, 2cg+1
            float2 w0 = make_float2(wv.x, wv.y), w1v = make_float2(wv.z, wv.w);
            const float2* ap = sA2 + kp * PA + 5 * rg;
            #pragma unroll
            for (int j = 0; j < 5; j++) {
                float2 aj = ap[j];
                fma2(acc[j][0], aj, w0);
                fma2(acc[j][1], aj, w1v);
            }
        }
        __syncthreads();
    }

    #pragma unroll
    for (int j = 0; j < 5; j++) {
        float* Cp = C + (size_t)(row0 + 5 * rg + j) * ldc + n0 + 2 * cg;
        atomicAdd(Cp + 0, acc[j][0].x + acc[j][0].y);
        atomicAdd(Cp + 1, acc[j][1].x + acc[j][1].y);
    }
}

// ---- final pair-GEMM unit (R10-verified body), one (px, bf, z) tile ----
struct FinalSmem {
    float sG[32 * (PB + 4)];
    float sWc[32 * 34];
    float sSc[H / KZ];
    int2  sIJ[PB];
};
__device__ void final_unit(const float* __restrict__ pe1b,
                           float* __restrict__ out_pred, float* __restrict__ out_ex,
                           int Nobj, int P, int Fh,
                           int px, int bf, int z, FinalSmem* fs, int tid)
{
    const int b = bf / Fh;
    const int p0 = px * PB;
    const int kz0 = z * (H / KZ);

    for (int i = tid; i < H / KZ; i += 256)
        fs->sSc[i] = g_Sc[(size_t)bf * H + kz0 + i] + pe1b[kz0 + i];
    if (tid < PB) {
        int nm1 = Nobj - 1;
        int pp = p0 + tid; if (pp >= P) pp = P - 1;
        int i = pp / nm1, r = pp % nm1; int j = (r < i) ? r : r + 1;
        fs->sIJ[tid] = make_int2(i, j);
    }
    __syncthreads();

    const int spair = tid >> 1;
    const int skh   = tid & 1;
    const float* saRow = g_Sa + (size_t)(b * Nobj + fs->sIJ[spair].x) * H + kz0;
    const float* sbRow = g_Sb + (size_t)(b * Nobj + fs->sIJ[spair].y) * H + kz0;

    const int pg = tid & 31;
    const int rg = tid >> 5;
    float2 acc[4][4];
    #pragma unroll
    for (int q = 0; q < 4; q++)
        #pragma unroll
        for (int s = 0; s < 4; s++) acc[q][s] = make_float2(0.f, 0.f);

    for (int kc = 0; kc < H / KZ; kc += 32) {
        #pragma unroll
        for (int j = 0; j < 4; j++) {
            int i = tid + j * 256;
            int r = i >> 5, k = i & 31;
            fs->sWc[r * 34 + k] = (r < 27) ? g_Wc[r * H + kz0 + kc + k] : 0.f;
        }
        #pragma unroll
        for (int j = 0; j < 4; j++) {
            int k = skh * 16 + j * 4;
            float4 a  = *(const float4*)(saRow + kc + k);
            float4 bv = *(const float4*)(sbRow + kc + k);
            float4 c4 = *(const float4*)(fs->sSc + kc + k);
            fs->sG[(k + 0) * (PB + 4) + spair] = gelu_f(a.x + bv.x + c4.x);
            fs->sG[(k + 1) * (PB + 4) + spair] = gelu_f(a.y + bv.y + c4.y);
            fs->sG[(k + 2) * (PB + 4) + spair] = gelu_f(a.z + bv.z + c4.z);
            fs->sG[(k + 3) * (PB + 4) + spair] = gelu_f(a.w + bv.w + c4.w);
        }
        __syncthreads();
        #pragma unroll
        for (int kk = 0; kk < 16; kk++) {
            float4 gA = *(const float4*)&fs->sG[(2 * kk)     * (PB + 4) + 4 * pg];
            float4 gB = *(const float4*)&fs->sG[(2 * kk + 1) * (PB + 4) + 4 * pg];
            float2 gp[4] = { make_float2(gA.x, gB.x), make_float2(gA.y, gB.y),
                             make_float2(gA.z, gB.z), make_float2(gA.w, gB.w) };
            #pragma unroll
            for (int s = 0; s < 4; s++) {
                float2 w = *(const float2*)&fs->sWc[(4 * rg + s) * 34 + 2 * kk];
                fma2(acc[0][s], gp[0], w);
                fma2(acc[1][s], gp[1], w);
                fma2(acc[2][s], gp[2], w);
                fma2(acc[3][s], gp[3], w);
            }
        }
        __syncthreads();
    }

    const float biasOn = (z == 0) ? 1.f : 0.f;
    #pragma unroll
    for (int q = 0; q < 4; q++) {
        int pair = p0 + 4 * pg + q;
        if (pair >= P) continue;
        size_t base = (size_t)bf * P + pair;
        #pragma unroll
        for (int s = 0; s < 4; s++) {
            int r = 4 * rg + s;
            if (r >= 27) continue;
            float v = acc[q][s].x + acc[q][s].y + biasOn * g_bc[r];
            if (r < NPREDC) atomicAdd(&out_pred[base * 26 + r], v);
            else            atomicAdd(&out_ex[base], v);
        }
    }
}

// ------------------------- persistent decoder (single kernel) -------------------------
__global__ __launch_bounds__(NT, 3) void decoder_kernel(Params p)
{
    __shared__ float2 sA[16 * PA];
    __shared__ float2 sW[16 * PW2];
    __shared__ FinalSmem fsm;
    const int tid = threadIdx.x, bid = blockIdx.x;
    const int lane = tid & 31;
    const int gw = bid * (NT / 32) + (tid >> 5);
    const int GW = gridDim.x * (NT / 32);
    const int GB = gridDim.x;
    const int M = p.B * p.Fh;
    const int Fh = p.Fh;

    auto zero4 = [&](float* pz, int n) {
        float4* z = (float4*)pz;
        int t4 = n >> 2;
        for (int i = bid * NT + tid; i < t4; i += GB * NT)
            z[i] = make_float4(0.f, 0.f, 0.f, 0.f);
    };
    // mt: row-tiles of 80; nt: col-tiles of 32; kz: k-slices of 64
    auto gemm_stage = [&](const float* A, int lda, const float* ab,
                          const float* W, int ldw, float* C, int ldc,
                          int mt, int nt, int kz) {
        int total = mt * nt * kz;
        for (int u = bid; u < total; u += GB) {
            int m = u % mt; int n = (u / mt) % nt; int z = u / (mt * nt);
            gemm_unit(A, lda, ab, W, ldw, C, ldc, m * 80, n * 32, z * 64, sA, sW, tid);
        }
    };
    auto attn_stage = [&](const float* Q, int ldq, const float* qb,
                          const float* K, const float* V, int ldkv,
                          const float* kb, const float* vb, int Tq, int Tk) {
        for (int u = gw; u < p.B * NH * Tq; u += GW) {
            int qi = u % Tq; int h = (u / Tq) % NH; int b = u / (Tq * NH);
            const float* qrow = Q + (size_t)(b * Tq + qi) * ldq + h * DH;
            float q0 = qrow[lane]      + qb[h * DH + lane];
            float q1 = qrow[lane + 32] + qb[h * DH + lane + 32];
            float kb0 = kb[h * DH + lane], kb1 = kb[h * DH + lane + 32];
            float vb0 = vb[h * DH + lane], vb1 = vb[h * DH + lane + 32];
            float s[TCTX];
            #pragma unroll
            for (int k = 0; k < TCTX; k++) {
                if (k < Tk) {
                    const float* krow = K + (size_t)(b * Tk + k) * ldkv + h * DH;
                    float pr = q0 * (krow[lane] + kb0) + q1 * (krow[lane + 32] + kb1);
                    #pragma unroll
                    for (int o = 16; o; o >>= 1) pr += __shfl_xor_sync(0xffffffffu, pr, o);
                    s[k] = pr * 0.125f;
                }
            }
            float mx = -1e30f;
            #pragma unroll
            for (int k = 0; k < TCTX; k++) if (k < Tk) mx = fmaxf(mx, s[k]);
            float sum = 0.f;
            #pragma unroll
            for (int k = 0; k < TCTX; k++) if (k < Tk) { s[k] = expf(s[k] - mx); sum += s[k]; }
            float inv = 1.f / sum;
            float o0 = 0.f, o1 = 0.f;
            #pragma unroll
            for (int k = 0; k < TCTX; k++) {
                if (k < Tk) {
                    const float* vrow = V + (size_t)(b * Tk + k) * ldkv + h * DH;
                    float a = s[k] * inv;
                    o0 += a * (vrow[lane] + vb0);
                    o1 += a * (vrow[lane + 32] + vb1);
                }
            }
            float* orow = g_ao + (size_t)(b * Tq + qi) * H + h * DH;
            orow[lane]      = o0;
            orow[lane + 32] = o1;
        }
    };
    auto ln_stage = [&](const float* src, const float* res, const float* cb,
                        float* dst, const float* w, const float* bnb) {
        for (int row = gw; row < M; row += GW) {
            const float* xr = src + (size_t)row * H;
            float4 v[4];
            float s = 0.f;
            #pragma unroll
            for (int i = 0; i < 4; i++) {
                int c = i * 128 + lane * 4;
                float4 t = *(const float4*)&xr[c];
                if (res) { float4 r = *(const float4*)&res[(size_t)row * H + c];
                           t.x += r.x; t.y += r.y; t.z += r.z; t.w += r.w; }
                if (cb)  { float4 b4 = *(const float4*)&cb[c];
                           t.x += b4.x; t.y += b4.y; t.z += b4.z; t.w += b4.w; }
                v[i] = t; s += t.x + t.y + t.z + t.w;
            }
            #pragma unroll
            for (int o = 16; o; o >>= 1) s += __shfl_xor_sync(0xffffffffu, s, o);
            float mean = s * (1.0f / H);
            float q = 0.f;
            #pragma unroll
            for (int i = 0; i < 4; i++) {
                float dx = v[i].x - mean, dy = v[i].y - mean, dz = v[i].z - mean, dw = v[i].w - mean;
                q += dx * dx + dy * dy + dz * dz + dw * dw;
            }
            #pragma unroll
            for (int o = 16; o; o >>= 1) q += __shfl_xor_sync(0xffffffffu, q, o);
            float inv = 1.0f / sqrtf(q * (1.0f / H) + 1e-5f);
            #pragma unroll
            for (int i = 0; i < 4; i++) {
                int c = i * 128 + lane * 4;
                float4 w4 = *(const float4*)&w[c];
                float4 b4 = *(const float4*)&bnb[c];
                float4 o4;
                o4.x = (v[i].x - mean) * inv * w4.x + b4.x;
                o4.y = (v[i].y - mean) * inv * w4.y + b4.y;
                o4.z = (v[i].z - mean) * inv * w4.z + b4.z;
                o4.w = (v[i].w - mean) * inv * w4.w + b4.w;
                *(float4*)&dst[(size_t)row * H + c] = o4;
            }
        }
    };

    // ---- Z0 ----
    zero4(g_qkv[0], M * 3 * H);  zero4(g_qkv[1], M * 3 * H);
    zero4(g_qb[0],  M * H);      zero4(g_qb[1],  M * H);
    zero4(g_kv[0],  p.B * TCTX * 2 * H); zero4(g_kv[1], p.B * TCTX * 2 * H);
    zero4(g_so[0],  M * H);      zero4(g_so[1],  M * H);
    zero4(g_co[0],  M * H);      zero4(g_co[1],  M * H);
    zero4(g_hh[0],  M * FFD);    zero4(g_hh[1],  M * FFD);
    zero4(g_ff[0],  M * H);      zero4(g_ff[1],  M * H);
    zero4(g_Sa, p.B * p.Nobj * H); zero4(g_Sb, p.B * p.Nobj * H);
    zero4(g_Sc, M * H);
    zero4(p.outp, p.outn);
    for (int i = bid * NT + tid; i < M * H; i += GB * NT) {
        int row = i / H, c = i % H;
        g_x[i] = p.fq[(row % Fh) * H + c];
    }
    for (int u = gw; u < 27 * 16; u += GW) {
        int rr = u / 16, cgp = u % 16;
        const float* Pr = (rr < NPREDC) ? (p.pred_w + rr * H) : p.ex_w;
        int c = cgp * 32 + lane;
        float a0 = 0.f, a1 = 0.f, a2 = 0.f, a3 = 0.f;
        for (int n = 0; n < H; n += 4) {
            a0 += Pr[n]     * p.pe2_w[(size_t)n * H + c];
            a1 += Pr[n + 1] * p.pe2_w[(size_t)(n + 1) * H + c];
            a2 += Pr[n + 2] * p.pe2_w[(size_t)(n + 2) * H + c];
            a3 += Pr[n + 3] * p.pe2_w[(size_t)(n + 3) * H + c];
        }
        g_Wc[rr * H + c] = (a0 + a1) + (a2 + a3);
    }
    for (int u = gw; u < 27; u += GW) {
        const float* Pr = (u < NPREDC) ? (p.pred_w + u * H) : p.ex_w;
        float s = 0.f;
        for (int n = lane; n < H; n += 32) s += Pr[n] * p.pe2_b[n];
        #pragma unroll
        for (int o = 16; o; o >>= 1) s += __shfl_xor_sync(0xffffffffu, s, o);
        if (lane == 0) g_bc[u] = s + ((u < NPREDC) ? p.pred_b[u] : p.ex_b[0]);
    }
    gsync();

    const int mS = (p.B * p.Nobj) / 80;   // 4
    const int mKV = (p.B * TCTX) / 80;    // 2

    // ---- S1 ----
    gemm_stage(g_x, H, nullptr, p.sa_in_w, H, g_qkv[0], 3 * H, 1, 3 * H / 32, 8);
    gemm_stage(p.objf, H, nullptr, p.pe1_w,     3 * H, g_Sa, H, mS, 16, 8);
    gemm_stage(p.objf, H, nullptr, p.pe1_w + H, 3 * H, g_Sb, H, mS, 16, 8);
    gemm_stage(p.tc, H, nullptr, p.ca_in_w + (size_t)H * H, H, g_kv[0], 2 * H, mKV, 2 * H / 32, 8);
    gsync();

    for (int l = 0; l < 2; l++) {
        const float* siw = p.sa_in_w  + (size_t)l * 3 * H * H;
        const float* sib = p.sa_in_b  + (size_t)l * 3 * H;
        const float* sow = p.sa_out_w + (size_t)l * H * H;
        const float* sob = p.sa_out_b + (size_t)l * H;
        const float* ciw = p.ca_in_w  + (size_t)l * 3 * H * H;
        const float* cib = p.ca_in_b  + (size_t)l * 3 * H;
        const float* cow = p.ca_out_w + (size_t)l * H * H;
        const float* cob = p.ca_out_b + (size_t)l * H;
        const float* f1w = p.ff1_w    + (size_t)l * FFD * H;
        const float* f1b = p.ff1_b    + (size_t)l * FFD;
        const float* f2w = p.ff2_w    + (size_t)l * H * FFD;
        const float* f2b = p.ff2_b    + (size_t)l * H;

        if (l == 1) {
            gemm_stage(g_x, H, nullptr, siw, H, g_qkv[1], 3 * H, 1, 3 * H / 32, 8);
            gemm_stage(p.tc, H, nullptr, ciw + (size_t)H * H, H, g_kv[1], 2 * H, mKV, 2 * H / 32, 8);
            gsync();
        }
        attn_stage(g_qkv[l], 3 * H, sib, g_qkv[l] + H, g_qkv[l] + 2 * H, 3 * H,
                   sib + H, sib + 2 * H, Fh, Fh);
        gsync();
        gemm_stage(g_ao, H, nullptr, sow, H, g_so[l], H, 1, 16, 8);
        gsync();
        ln_stage(g_so[l], g_x, sob, g_x, p.n1_w + l * H, p.n1_b + l * H);
        gsync();
        gemm_stage(g_x, H, nullptr, ciw, H, g_qb[l], H, 1, 16, 8);
        gsync();
        attn_stage(g_qb[l], H, cib, g_kv[l], g_kv[l] + H, 2 * H,
                   cib + H, cib + 2 * H, Fh, TCTX);
        gsync();
        gemm_stage(g_ao, H, nullptr, cow, H, g_co[l], H, 1, 16, 8);
        gsync();
        ln_stage(g_co[l], g_x, cob, g_x, p.n2_w + l * H, p.n2_b + l * H);
        gsync();
        gemm_stage(g_x, H, nullptr, f1w, H, g_hh[l], FFD, 1, FFD / 32, 8);
        gsync();
        gemm_stage(g_hh[l], FFD, f1b, f2w, FFD, g_ff[l], H, 1, 16, FFD / 64);
        gsync();
        ln_stage(g_ff[l], g_x, f2b, g_x, p.n3_w + l * H, p.n3_b + l * H);
        gsync();
    }

    ln_stage(g_x, nullptr, nullptr, g_ctx, p.norm_w, p.norm_b);
    gsync();
    gemm_stage(g_ctx, H, nullptr, p.pe1_w + 2 * H, 3 * H, g_Sc, H, 1, 16, 8);
    gsync();

    // ---- final stage: pair GEMM into d_out ----
    {
        int P = p.Nobj * (p.Nobj - 1);
        int PBx = (P + PB - 1) / PB;
        float* out_pred = p.outp;
        float* out_ex   = p.outp + (size_t)p.B * p.Fh * P * NPREDC;
        int total = PBx * M * KZ;
        for (int u = bid; u < total; u += GB) {
            int px = u % PBx;
            int bf = (u / PBx) % M;
            int z  = u / (PBx * M);
            final_unit(p.pe1_b, out_pred, out_ex, p.Nobj, P, Fh, px, bf, z, &fsm, tid);
        }
    }
}

// ------------------------- host launcher -------------------------
extern "C" void kernel_launch(void* const* d_in, const int* in_sizes, int n_in,
                              void* d_out, int out_size)
{
    Params p;
    p.tc       = (const float*)d_in[0];
    p.objf     = (const float*)d_in[1];
    p.fq       = (const float*)d_in[2];
    p.sa_in_w  = (const float*)d_in[3];
    p.sa_in_b  = (const float*)d_in[4];
    p.sa_out_w = (const float*)d_in[5];
    p.sa_out_b = (const float*)d_in[6];
    p.ca_in_w  = (const float*)d_in[7];
    p.ca_in_b  = (const float*)d_in[8];
    p.ca_out_w = (const float*)d_in[9];
    p.ca_out_b = (const float*)d_in[10];
    p.ff1_w    = (const float*)d_in[11];
    p.ff1_b    = (const float*)d_in[12];
    p.ff2_w    = (const float*)d_in[13];
    p.ff2_b    = (const float*)d_in[14];
    p.n1_w     = (const float*)d_in[15];
    p.n1_b     = (const float*)d_in[16];
    p.n2_w     = (const float*)d_in[17];
    p.n2_b     = (const float*)d_in[18];
    p.n3_w     = (const float*)d_in[19];
    p.n3_b     = (const float*)d_in[20];
    p.norm_w   = (const float*)d_in[21];
    p.norm_b   = (const float*)d_in[22];
    p.pe1_w    = (const float*)d_in[23];
    p.pe1_b    = (const float*)d_in[24];
    p.pe2_w    = (const float*)d_in[25];
    p.pe2_b    = (const float*)d_in[26];
    p.pred_w   = (const float*)d_in[27];
    p.pred_b   = (const float*)d_in[28];
    p.ex_w     = (const float*)d_in[29];
    p.ex_b     = (const float*)d_in[30];

    p.B    = in_sizes[0] / (TCTX * H);
    p.Nobj = in_sizes[1] / (p.B * H);
    int P  = p.Nobj * (p.Nobj - 1);
    p.Fh   = out_size / (p.B * P * (NPREDC + 1));
    p.outp = (float*)d_out;
    p.outn = out_size;

    decoder_kernel<<<NB, NT>>>(p);
}